// round 17
// baseline (speedup 1.0000x reference)
#include <cuda_runtime.h>
#include <cstdint>

// MAM dense: C[m,n] = max_k(A[m,k]*W[n,k]) + min_k(A[m,k]*W[n,k]) + bias[n]
// A:[M,K], W:[N,K], bias:[N], C:[M,N], fp32. M=2048, K=1024, N=1024.
//
// R7 structure (best known: 174us): 2-stage cp.async, BK=32, PAD=36,
// mul.rn.f32x2 packed products (FMNMX2 does NOT exist -> scalar max/min).
// R14 change: __launch_bounds__(128, 6) to force regs<=85 and raise
// occupancy 5->6 (20->24 warps/SM) for FMNMX/LDS latency hiding.

#define BM 64
#define BN 32
#define BK 32
#define PAD 36    // floats per smem row = 144B = 9 x 16B (odd -> conflict-free)
#define NT 128

typedef unsigned long long ull;

__device__ __forceinline__ ull mul2(ull a, ull b) {
    ull r;
    asm("mul.rn.f32x2 %0, %1, %2;" : "=l"(r) : "l"(a), "l"(b));
    return r;
}
__device__ __forceinline__ void unpack2(ull d, float& lo, float& hi) {
    asm("mov.b64 {%0, %1}, %2;" : "=f"(lo), "=f"(hi) : "l"(d));
}

__global__ __launch_bounds__(NT, 6)
void mam_dense_kernel(const float* __restrict__ A,
                      const float* __restrict__ W,
                      const float* __restrict__ bias,
                      float* __restrict__ C,
                      int M, int N, int K) {
    __shared__ float As[2][BM * PAD];
    __shared__ float Bs[2][BN * PAD];

    const int t  = threadIdx.x;
    const int tx = t & 7;     // n-direction (8)
    const int ty = t >> 3;    // m-direction (16)

    const int rowBase = blockIdx.y * BM;
    const int colBase = blockIdx.x * BN;

    // cp.async mapping
    const int lrow = t >> 3;        // 0..15
    const int lq   = (t & 7) * 4;   // float offset within row: 0,4,...,28

    const float* aG = A + (size_t)(rowBase + lrow) * K + lq;
    const float* bG = W + (size_t)(colBase + lrow) * K + lq;

    const uint32_t asB0 = (uint32_t)__cvta_generic_to_shared(&As[0][0]);
    const uint32_t asB1 = (uint32_t)__cvta_generic_to_shared(&As[1][0]);
    const uint32_t bsB0 = (uint32_t)__cvta_generic_to_shared(&Bs[0][0]);
    const uint32_t bsB1 = (uint32_t)__cvta_generic_to_shared(&Bs[1][0]);
    const uint32_t sOff = (uint32_t)(lrow * PAD + lq) * 4u;

#define LOAD_BLOCK(KB, BUF)                                                          \
    do {                                                                             \
        const float* a0 = aG + (KB) * BK;                                            \
        const float* b0 = bG + (KB) * BK;                                            \
        uint32_t ad = ((BUF) ? asB1 : asB0) + sOff;                                  \
        uint32_t bd = ((BUF) ? bsB1 : bsB0) + sOff;                                  \
        _Pragma("unroll")                                                            \
        for (int i = 0; i < 4; ++i)                                                  \
            asm volatile("cp.async.cg.shared.global [%0], [%1], 16;\n" ::            \
                         "r"(ad + (uint32_t)(i * 16 * PAD * 4)),                     \
                         "l"(a0 + (size_t)i * 16 * K));                              \
        _Pragma("unroll")                                                            \
        for (int i = 0; i < 2; ++i)                                                  \
            asm volatile("cp.async.cg.shared.global [%0], [%1], 16;\n" ::            \
                         "r"(bd + (uint32_t)(i * 16 * PAD * 4)),                     \
                         "l"(b0 + (size_t)i * 16 * K));                              \
        asm volatile("cp.async.commit_group;\n");                                    \
    } while (0)

    float mx[4][4], mn[4][4];
#pragma unroll
    for (int i = 0; i < 4; ++i)
#pragma unroll
        for (int j = 0; j < 4; ++j) {
            mx[i][j] = -3.402823466e38f;
            mn[i][j] =  3.402823466e38f;
        }

    const int NKB = K / BK;

    LOAD_BLOCK(0, 0);

    for (int kb = 0; kb < NKB; ++kb) {
        const int buf = kb & 1;
        asm volatile("cp.async.wait_group 0;\n" ::: "memory");
        __syncthreads();
        if (kb + 1 < NKB) {
            if (buf) LOAD_BLOCK(kb + 1, 0);
            else     LOAD_BLOCK(kb + 1, 1);
        }

        const float* as = As[buf];
        const float* bs = Bs[buf];
#pragma unroll
        for (int kq = 0; kq < BK / 4; ++kq) {
            // each ulonglong2 = 4 consecutive k-values as two packed f32 pairs
            ulonglong2 av[4], bv[4];
#pragma unroll
            for (int i = 0; i < 4; ++i)
                av[i] = *(const ulonglong2*)(as + (ty * 4 + i) * PAD + kq * 4);
#pragma unroll
            for (int j = 0; j < 4; ++j)
                bv[j] = *(const ulonglong2*)(bs + (tx + 8 * j) * PAD + kq * 4);
#pragma unroll
            for (int i = 0; i < 4; ++i) {
#pragma unroll
                for (int j = 0; j < 4; ++j) {
                    ull d0 = mul2(av[i].x, bv[j].x);  // p(k0), p(k1)
                    ull d1 = mul2(av[i].y, bv[j].y);  // p(k2), p(k3)
                    float p0, p1, p2, p3;
                    unpack2(d0, p0, p1);
                    unpack2(d1, p2, p3);
                    mx[i][j] = fmaxf(mx[i][j], p0); mn[i][j] = fminf(mn[i][j], p0);
                    mx[i][j] = fmaxf(mx[i][j], p1); mn[i][j] = fminf(mn[i][j], p1);
                    mx[i][j] = fmaxf(mx[i][j], p2); mn[i][j] = fminf(mn[i][j], p2);
                    mx[i][j] = fmaxf(mx[i][j], p3); mn[i][j] = fminf(mn[i][j], p3);
                }
            }
        }
        // next iteration's wait+sync protects the buffer we just read
    }

    // epilogue: C = mx + mn + bias
    float bb[4];
#pragma unroll
    for (int j = 0; j < 4; ++j)
        bb[j] = bias[colBase + tx + 8 * j];

#pragma unroll
    for (int i = 0; i < 4; ++i) {
        const size_t rowOff = (size_t)(rowBase + ty * 4 + i) * N + colBase;
#pragma unroll
        for (int j = 0; j < 4; ++j)
            C[rowOff + tx + 8 * j] = mx[i][j] + mn[i][j] + bb[j];
    }
#undef LOAD_BLOCK
}

extern "C" void kernel_launch(void* const* d_in, const int* in_sizes, int n_in,
                              void* d_out, int out_size) {
    const float* x      = (const float*)d_in[0];   // [M, K]
    const float* weight = (const float*)d_in[1];   // [N, K]
    const float* bias   = (const float*)d_in[2];   // [N]
    float* out          = (float*)d_out;           // [M, N]

    const int N = in_sizes[2];
    const int K = in_sizes[1] / N;
    const int M = in_sizes[0] / K;

    dim3 grid(N / BN, M / BM);   // (32, 32) = 1024 CTAs -> ~6.9 per SM
    mam_dense_kernel<<<grid, NT>>>(x, weight, bias, out, M, N, K);
}